// round 15
// baseline (speedup 1.0000x reference)
#include <cuda_runtime.h>
#include <cstdint>

#define S1STR   13824
#define S2STR   576
#define STOT    331776          // 24^4
#define CIN     8
#define COUT    16
#define XIMG    (CIN * STOT)
#define OIMG    (COUT * STOT)

#define THREADS 288             // 9 warps, 64 positions each
#define NBLK    (8 * 24 * 24)

// x buffer: padded position grid 26 rows x 28 cols, 8 words (channels) per cell
#define PC      28
#define XS_W    (26 * PC * 8)   // 5824 words
#define WF_W    (81 * 32 * 4)   // per-lane B fragments
#define SMEM_BYTES ((XS_W + WF_W) * 4)   // 64768 B
#define EPI_STR 580

__device__ __forceinline__ unsigned tf32r(float f) {
    unsigned r; asm("cvt.rna.tf32.f32 %0, %1;" : "=r"(r) : "f"(f)); return r;
}

__device__ __forceinline__ void mma_tf32(float d[4],
                                         unsigned a0, unsigned a1,
                                         unsigned a2, unsigned a3,
                                         unsigned b0, unsigned b1) {
    asm volatile(
        "mma.sync.aligned.m16n8k8.row.col.f32.tf32.tf32.f32 "
        "{%0,%1,%2,%3}, {%4,%5,%6,%7}, {%8,%9}, {%0,%1,%2,%3};"
        : "+f"(d[0]), "+f"(d[1]), "+f"(d[2]), "+f"(d[3])
        : "r"(a0), "r"(a1), "r"(a2), "r"(a3), "r"(b0), "r"(b1));
}

__global__ __launch_bounds__(THREADS, 2)
void conv4d_mma_kernel(const float* __restrict__ x,
                       const float* __restrict__ w,
                       const float* __restrict__ bias,
                       float* __restrict__ out) {
    extern __shared__ float smem[];
    float* xs    = smem;            // [cell(26x28)][chan-slot(8)]
    float* wfrag = smem + XS_W;

    const int tid  = threadIdx.x;
    const int lane = tid & 31;
    const int warp = tid >> 5;
    const int tg   = lane & 3;
    const int grp  = lane >> 2;

    int bid = blockIdx.x;
    int s2 = bid % 24; int t = bid / 24;
    int s1 = t % 24;   int b = t / 24;

    // ---- B fragments per lane (tf32-rounded), identical layout to R12 ----
    for (int i = tid; i < WF_W; i += THREADS) {
        int q  = i & 3;
        int l  = (i >> 2) & 31;
        int tap = i >> 7;
        int c = (l & 3) + (q & 1) * 4;
        int o = (l >> 2) + (q >> 1) * 8;
        wfrag[i] = __uint_as_float(tf32r(w[o * 648 + tap * 8 + c]));
    }
    for (int i = tid; i < XS_W; i += THREADS) xs[i] = 0.0f;

    // ---- per-thread staging offsets ----
    // j -> c = j&7 (channel), pq = j>>3 : s3 = pq/6, s4g = (pq%6)*4
    // channel slot permutation: slot = 2*(c&3) + (c>>2)  (k=tg,k=tg+4 adjacent)
    int soff[4], dbase[4], pqv[4];
    #pragma unroll
    for (int i = 0; i < 4; ++i) {
        int j = i * THREADS + tid;       // 0..1151
        int c  = j & 7;
        int pq = j >> 3;
        int s3 = pq / 6, s4g = (pq - s3 * 6) * 4;
        int slot = 2 * (c & 3) + (c >> 2);
        soff[i]  = c * STOT + s3 * 24 + s4g;
        dbase[i] = ((s3 + 1) * PC + s4g + 1) * 8 + slot;
        pqv[i]   = pq;
    }

    // ---- accumulators (bias-initialized) ----
    float bv0 = bias[2 * tg],     bv1 = bias[2 * tg + 1];
    float bv2 = bias[2 * tg + 8], bv3 = bias[2 * tg + 9];
    float d[4][2][4];
    #pragma unroll
    for (int i = 0; i < 4; ++i) {
        d[i][0][0] = bv0; d[i][0][1] = bv1; d[i][0][2] = bv0; d[i][0][3] = bv1;
        d[i][1][0] = bv2; d[i][1][1] = bv3; d[i][1][2] = bv2; d[i][1][3] = bv3;
    }

    // ---- per-mtile A word offsets: cell(P)*8 + 2*tg ----
    int A0[4], A1[4];
    #pragma unroll
    for (int i = 0; i < 4; ++i) {
        int P0 = warp * 64 + i * 16 + grp;
        int P1 = P0 + 8;
        A0[i] = ((P0 / 24) * PC + (P0 % 24)) * 8 + 2 * tg;
        A1[i] = ((P1 / 24) * PC + (P1 % 24)) * 8 + 2 * tg;
    }

    // ---- valid (k1,k2) plane list ----
    const float* __restrict__ xb = x + (size_t)b * XIMG;
    const float* psrc[9]; int ptb[9]; int nv = 0;
    #pragma unroll
    for (int k1 = 0; k1 < 3; ++k1) {
        int p1 = s1 + k1 - 1;
        if ((unsigned)p1 >= 24u) continue;
        #pragma unroll
        for (int k2 = 0; k2 < 3; ++k2) {
            int p2 = s2 + k2 - 1;
            if ((unsigned)p2 >= 24u) continue;
            psrc[nv] = xb + p1 * S1STR + p2 * S2STR;
            ptb[nv]  = (k1 * 3 + k2) * 9;
            ++nv;
        }
    }

    // ---- prologue: fetch plane 0 into registers ----
    float4 r0 = *reinterpret_cast<const float4*>(psrc[0] + soff[0]);
    float4 r1 = *reinterpret_cast<const float4*>(psrc[0] + soff[1]);
    float4 r2 = *reinterpret_cast<const float4*>(psrc[0] + soff[2]);
    float4 r3 = *reinterpret_cast<const float4*>(psrc[0] + soff[3]);

    __syncthreads();   // zeros + wfrag visible

    #pragma unroll 1
    for (int ip = 0; ip < nv; ++ip) {
        // deposit current plane: rotated STS.32 (conflict-free)
        #pragma unroll
        for (int s = 0; s < 4; ++s) {
            {   int u = (s + pqv[0]) & 3;
                float v = (u & 2) ? ((u & 1) ? r0.w : r0.z)
                                  : ((u & 1) ? r0.y : r0.x);
                xs[dbase[0] + u * 8] = v; }
            {   int u = (s + pqv[1]) & 3;
                float v = (u & 2) ? ((u & 1) ? r1.w : r1.z)
                                  : ((u & 1) ? r1.y : r1.x);
                xs[dbase[1] + u * 8] = v; }
            {   int u = (s + pqv[2]) & 3;
                float v = (u & 2) ? ((u & 1) ? r2.w : r2.z)
                                  : ((u & 1) ? r2.y : r2.x);
                xs[dbase[2] + u * 8] = v; }
            {   int u = (s + pqv[3]) & 3;
                float v = (u & 2) ? ((u & 1) ? r3.w : r3.z)
                                  : ((u & 1) ? r3.y : r3.x);
                xs[dbase[3] + u * 8] = v; }
        }
        // kick off next plane's loads; latency hides under compute
        if (ip + 1 < nv) {
            const float* s = psrc[ip + 1];
            r0 = *reinterpret_cast<const float4*>(s + soff[0]);
            r1 = *reinterpret_cast<const float4*>(s + soff[1]);
            r2 = *reinterpret_cast<const float4*>(s + soff[2]);
            r3 = *reinterpret_cast<const float4*>(s + soff[3]);
        }
        __syncthreads();   // plane ip visible

        // ---- B fragments: one LDS.128 per tap ----
        int tb = ptb[ip];
        float4 bf[9];
        #pragma unroll
        for (int t9 = 0; t9 < 9; ++t9)
            bf[t9] = *reinterpret_cast<const float4*>(
                &wfrag[((tb + t9) * 32 + lane) * 4]);

        // ---- compute: 4 m-tiles x 9 taps, A via 2 LDS.64 each ----
        #pragma unroll
        for (int i = 0; i < 4; ++i) {
            #pragma unroll
            for (int t9 = 0; t9 < 9; ++t9) {
                int off = (t9 / 3) * (PC * 8) + (t9 % 3) * 8;
                float2 lo = *reinterpret_cast<const float2*>(&xs[A0[i] + off]);
                float2 hi = *reinterpret_cast<const float2*>(&xs[A1[i] + off]);
                mma_tf32(d[i][0],
                         __float_as_uint(lo.x), __float_as_uint(hi.x),
                         __float_as_uint(lo.y), __float_as_uint(hi.y),
                         __float_as_uint(bf[t9].x), __float_as_uint(bf[t9].y));
                mma_tf32(d[i][1],
                         __float_as_uint(lo.x), __float_as_uint(hi.x),
                         __float_as_uint(lo.y), __float_as_uint(hi.y),
                         __float_as_uint(bf[t9].z), __float_as_uint(bf[t9].w));
            }
        }
        __syncthreads();   // compute done before buffer is re-staged
    }

    // ---- epilogue: transpose via smem, coalesced STG.128 ----
    size_t ob = (size_t)b * OIMG + (size_t)(s1 * S1STR + s2 * S2STR);
    #pragma unroll 1
    for (int half = 0; half < 2; ++half) {
        __syncthreads();
        #pragma unroll
        for (int i = 0; i < 4; ++i) {
            int P0 = warp * 64 + i * 16 + grp;
            int P1 = P0 + 8;
            int o0 = 2 * tg;
            smem[o0 * EPI_STR + P0]       = d[i][half][0];
            smem[(o0 + 1) * EPI_STR + P0] = d[i][half][1];
            smem[o0 * EPI_STR + P1]       = d[i][half][2];
            smem[(o0 + 1) * EPI_STR + P1] = d[i][half][3];
        }
        __syncthreads();
        int o  = tid / 36;
        int ch = tid % 36;
        const float4* se = reinterpret_cast<const float4*>(&smem[o * EPI_STR + ch * 16]);
        float4* de = reinterpret_cast<float4*>(
            out + ob + (size_t)(half * 8 + o) * STOT + ch * 16);
        de[0] = se[0]; de[1] = se[1]; de[2] = se[2]; de[3] = se[3];
    }
}

extern "C" void kernel_launch(void* const* d_in, const int* in_sizes, int n_in,
                              void* d_out, int out_size) {
    const float* x    = (const float*)d_in[0];
    const float* wgt  = (const float*)d_in[1];
    const float* bias = (const float*)d_in[2];
    float* out = (float*)d_out;
    (void)in_sizes; (void)n_in; (void)out_size;

    cudaFuncSetAttribute(conv4d_mma_kernel,
                         cudaFuncAttributeMaxDynamicSharedMemorySize, SMEM_BYTES);
    conv4d_mma_kernel<<<NBLK, THREADS, SMEM_BYTES>>>(x, wgt, bias, out);
}

// round 16
// speedup vs baseline: 1.3676x; 1.3676x over previous
#include <cuda_runtime.h>
#include <cstdint>

#define S1STR   13824
#define S2STR   576
#define STOT    331776          // 24^4
#define CIN     8
#define COUT    16
#define XIMG    (CIN * STOT)
#define OIMG    (COUT * STOT)

#define THREADS 384             // 12 warps, 48 positions each
#define NBLK    (8 * 24 * 24)

// padded x plane: per channel 26 rows x 32 cols -> pitch 840 words
#define XPW     840
#define XS_W    (CIN * XPW)     // 6720 words
#define WF_W    (81 * 32 * 4)   // wfrag[(tap*32+lane)*4+q]
#define SMEM_BYTES ((XS_W + WF_W) * 4)   // 68352 B
#define EPI_STR 580

__device__ __forceinline__ unsigned tf32r(float f) {
    unsigned r; asm("cvt.rna.tf32.f32 %0, %1;" : "=r"(r) : "f"(f)); return r;
}

__device__ __forceinline__ void mma_tf32(float d[4],
                                         unsigned a0, unsigned a1,
                                         unsigned a2, unsigned a3,
                                         unsigned b0, unsigned b1) {
    asm volatile(
        "mma.sync.aligned.m16n8k8.row.col.f32.tf32.tf32.f32 "
        "{%0,%1,%2,%3}, {%4,%5,%6,%7}, {%8,%9}, {%0,%1,%2,%3};"
        : "+f"(d[0]), "+f"(d[1]), "+f"(d[2]), "+f"(d[3])
        : "r"(a0), "r"(a1), "r"(a2), "r"(a3), "r"(b0), "r"(b1));
}

__global__ __launch_bounds__(THREADS, 2)
void conv4d_mma_kernel(const float* __restrict__ x,
                       const float* __restrict__ w,
                       const float* __restrict__ bias,
                       float* __restrict__ out) {
    extern __shared__ float smem[];
    float* xs    = smem;            // single x buffer, [chan][26x32 padded plane]
    float* wfrag = smem + XS_W;     // per-lane B fragments

    const int tid  = threadIdx.x;
    const int lane = tid & 31;
    const int warp = tid >> 5;          // 0..11
    const int tg   = lane & 3;
    const int grp  = lane >> 2;

    int bid = blockIdx.x;
    int s2 = bid % 24; int t = bid / 24;
    int s1 = t % 24;   int b = t / 24;

    // ---- stage B fragments per lane (tf32-rounded) ----
    for (int i = tid; i < WF_W; i += THREADS) {
        int q  = i & 3;
        int l  = (i >> 2) & 31;
        int tap = i >> 7;
        int c = (l & 3) + (q & 1) * 4;
        int o = (l >> 2) + (q >> 1) * 8;
        wfrag[i] = __uint_as_float(tf32r(w[o * 648 + tap * 8 + c]));
    }
    for (int i = tid; i < XS_W; i += THREADS) xs[i] = 0.0f;

    // ---- per-thread staging offsets (3 float4 per thread) ----
    int soff[3], doff[3];
    #pragma unroll
    for (int i = 0; i < 3; ++i) {
        int j = i * THREADS + tid;       // 0..1151
        int row = j / 6, seg = j - row * 6;
        int c = row / 24, s3 = row - c * 24;
        soff[i] = c * STOT + s3 * 24 + seg * 4;
        doff[i] = c * XPW + (s3 + 1) * 32 + 4 + seg * 4;
    }

    // ---- accumulators (bias-initialized): d[3 tiles][2 n-halves][4] ----
    float bv0 = bias[2 * tg],     bv1 = bias[2 * tg + 1];
    float bv2 = bias[2 * tg + 8], bv3 = bias[2 * tg + 9];
    float d[3][2][4];
    #pragma unroll
    for (int i = 0; i < 3; ++i) {
        d[i][0][0] = bv0; d[i][0][1] = bv1; d[i][0][2] = bv0; d[i][0][3] = bv1;
        d[i][1][0] = bv2; d[i][1][1] = bv3; d[i][1][2] = bv2; d[i][1][3] = bv3;
    }

    // ---- per-tile A base word offsets ----
    int A0[3], A1[3];
    #pragma unroll
    for (int i = 0; i < 3; ++i) {
        int P0 = warp * 48 + i * 16 + grp;
        int P1 = P0 + 8;
        A0[i] = tg * XPW + (P0 / 24) * 32 + (P0 % 24) + 3;
        A1[i] = tg * XPW + (P1 / 24) * 32 + (P1 % 24) + 3;
    }

    // ---- valid (k1,k2) plane list, packed: code = word_off*128 + tap_base ----
    const float* __restrict__ xb = x + (size_t)b * XIMG;
    int pcode[9]; int nv = 0;
    #pragma unroll
    for (int k1 = 0; k1 < 3; ++k1) {
        int p1 = s1 + k1 - 1;
        if ((unsigned)p1 >= 24u) continue;
        #pragma unroll
        for (int k2 = 0; k2 < 3; ++k2) {
            int p2 = s2 + k2 - 1;
            if ((unsigned)p2 >= 24u) continue;
            pcode[nv++] = (p1 * S1STR + p2 * S2STR) * 128 + (k1 * 3 + k2) * 9;
        }
    }

    // ---- prologue: fetch plane 0 into registers ----
    const float* s0 = xb + (pcode[0] >> 7);
    float4 r0 = *reinterpret_cast<const float4*>(s0 + soff[0]);
    float4 r1 = *reinterpret_cast<const float4*>(s0 + soff[1]);
    float4 r2 = *reinterpret_cast<const float4*>(s0 + soff[2]);

    __syncthreads();   // zeros + wfrag visible

    #pragma unroll 1
    for (int ip = 0; ip < nv; ++ip) {
        int tb = pcode[ip] & 127;
        // deposit current plane (raw f32; MMA truncates to tf32)
        *reinterpret_cast<float4*>(&xs[doff[0]]) = r0;
        *reinterpret_cast<float4*>(&xs[doff[1]]) = r1;
        *reinterpret_cast<float4*>(&xs[doff[2]]) = r2;
        // prefetch next plane; latency hides under compute
        if (ip + 1 < nv) {
            const float* s = xb + (pcode[ip + 1] >> 7);
            r0 = *reinterpret_cast<const float4*>(s + soff[0]);
            r1 = *reinterpret_cast<const float4*>(s + soff[1]);
            r2 = *reinterpret_cast<const float4*>(s + soff[2]);
        }
        __syncthreads();   // plane ip visible

        // ---- compute: t9 outer (1 live B-frag), 3 tiles inner ----
        #pragma unroll
        for (int t9 = 0; t9 < 9; ++t9) {
            float4 bf = *reinterpret_cast<const float4*>(
                &wfrag[((tb + t9) * 32 + lane) * 4]);
            int off = (t9 / 3) * 32 + (t9 % 3);   // k3*32 + k4
            #pragma unroll
            for (int i = 0; i < 3; ++i) {
                unsigned a0 = __float_as_uint(xs[A0[i] + off]);
                unsigned a1 = __float_as_uint(xs[A1[i] + off]);
                unsigned a2 = __float_as_uint(xs[A0[i] + off + 4 * XPW]);
                unsigned a3 = __float_as_uint(xs[A1[i] + off + 4 * XPW]);
                mma_tf32(d[i][0], a0, a1, a2, a3,
                         __float_as_uint(bf.x), __float_as_uint(bf.y));
                mma_tf32(d[i][1], a0, a1, a2, a3,
                         __float_as_uint(bf.z), __float_as_uint(bf.w));
            }
        }
        __syncthreads();   // compute done before buffer is re-staged
    }

    // ---- epilogue: transpose via smem, coalesced STG.128 ----
    size_t ob = (size_t)b * OIMG + (size_t)(s1 * S1STR + s2 * S2STR);
    #pragma unroll 1
    for (int half = 0; half < 2; ++half) {
        __syncthreads();
        #pragma unroll
        for (int i = 0; i < 3; ++i) {
            int P0 = warp * 48 + i * 16 + grp;
            int P1 = P0 + 8;
            int o0 = 2 * tg;
            smem[o0 * EPI_STR + P0]       = d[i][half][0];
            smem[(o0 + 1) * EPI_STR + P0] = d[i][half][1];
            smem[o0 * EPI_STR + P1]       = d[i][half][2];
            smem[(o0 + 1) * EPI_STR + P1] = d[i][half][3];
        }
        __syncthreads();
        if (tid < 288) {
            int o  = tid / 36;
            int ch = tid % 36;
            const float4* se = reinterpret_cast<const float4*>(
                &smem[o * EPI_STR + ch * 16]);
            float4* de = reinterpret_cast<float4*>(
                out + ob + (size_t)(half * 8 + o) * STOT + ch * 16);
            de[0] = se[0]; de[1] = se[1]; de[2] = se[2]; de[3] = se[3];
        }
    }
}

extern "C" void kernel_launch(void* const* d_in, const int* in_sizes, int n_in,
                              void* d_out, int out_size) {
    const float* x    = (const float*)d_in[0];
    const float* wgt  = (const float*)d_in[1];
    const float* bias = (const float*)d_in[2];
    float* out = (float*)d_out;
    (void)in_sizes; (void)n_in; (void)out_size;

    cudaFuncSetAttribute(conv4d_mma_kernel,
                         cudaFuncAttributeMaxDynamicSharedMemorySize, SMEM_BYTES);
    conv4d_mma_kernel<<<NBLK, THREADS, SMEM_BYTES>>>(x, wgt, bias, out);
}